// round 8
// baseline (speedup 1.0000x reference)
#include <cuda_runtime.h>
#include <cuda_fp16.h>
#include <cstdint>
#include <cstddef>

#define NPTS   4096
#define MANCH  128
#define GC0    64
#define GC1    128
#define KNN    32
#define RR2    0.0225f
#define GTOT   64
#define FPS_THREADS 1024
#define CONV_THREADS 256
#define BSTRIDE 34   // words per k-row in B buffer (32 half2 pairs + pad)

// Layer-1 weights (1KB — const-cache resident, warp-uniform reads)
__constant__ float4 cWd[GC0];
// Layer-2 weights as fp16x2, pre-swizzled into m16n8k16 A-fragment layout:
// [mt(8)][kt(4)][lane(32)][r(4)]  (4096 words = 16KB, L1-resident)
__device__ uint32_t gWmF16[8 * 4 * 128];

// Exact (non-FMA-contracted) squared distance: discrete decisions
// (FPS argmax / radius threshold) match the JAX reference bit-for-bit.
__device__ __forceinline__ float dist2_precise(float ax, float ay, float az,
                                               float bx, float by, float bz) {
    float dx = __fsub_rn(ax, bx);
    float dy = __fsub_rn(ay, by);
    float dz = __fsub_rn(az, bz);
    return __fadd_rn(__fadd_rn(__fmul_rn(dx, dx), __fmul_rn(dy, dy)),
                     __fmul_rn(dz, dz));
}

// pack two fp32 -> fp16x2 (lo in low half)
__device__ __forceinline__ uint32_t pkh2(float lo, float hi) {
    uint32_t r;
    asm("cvt.rn.f16x2.f32 %0, %1, %2;" : "=r"(r) : "f"(hi), "f"(lo));
    return r;
}

__device__ __forceinline__ void mma_f16(float& d0, float& d1, float& d2, float& d3,
                                        uint32_t a0, uint32_t a1, uint32_t a2, uint32_t a3,
                                        uint32_t b0, uint32_t b1) {
    asm volatile(
        "mma.sync.aligned.m16n8k16.row.col.f32.f16.f16.f32 "
        "{%0,%1,%2,%3}, {%4,%5,%6,%7}, {%8,%9}, {%0,%1,%2,%3};"
        : "+f"(d0), "+f"(d1), "+f"(d2), "+f"(d3)
        : "r"(a0), "r"(a1), "r"(a2), "r"(a3), "r"(b0), "r"(b1));
}

// ---------------------------------------------------------------------------
// Prep: Wm -> fp16x2 A-fragments (m16n8k16 layout). 4096 threads, 1 word each.
// ---------------------------------------------------------------------------
__global__ void prep_kernel(const float* __restrict__ Wm) {
    int idx = blockIdx.x * blockDim.x + threadIdx.x;  // 0..4095
    int r = idx & 3;
    int l = (idx >> 2) & 31;
    int fid = idx >> 7;          // 0..31 = mt*4 + kt
    int kt = fid & 3, mt = fid >> 2;
    int gid = l >> 2, tig = l & 3;
    int row = mt * 16 + gid + (r & 1) * 8;          // o index
    int ch  = kt * 16 + tig * 2 + (r >> 1) * 8;     // channel (even)
    gWmF16[idx] = pkh2(Wm[row * GC0 + ch], Wm[row * GC0 + ch + 1]);
}

// ---------------------------------------------------------------------------
// Kernel A: furthest point sampling (exact fp32).
// ---------------------------------------------------------------------------
__global__ void __launch_bounds__(FPS_THREADS) fps_kernel(
    const float* __restrict__ xyzs, float* __restrict__ out) {
    extern __shared__ float sm[];
    float* sx = sm;
    float* sy = sm + NPTS;
    float* sz = sm + 2 * NPTS;
    __shared__ float redV[32];
    __shared__ int   redI[32];
    __shared__ float curP[3];

    int g = blockIdx.x;
    int b = g >> 4, f = g & 15;
    int t = 2 * f;
    const float* frame = xyzs + ((size_t)(b * 32 + t)) * NPTS * 3;
    int tid = threadIdx.x;

    for (int i = tid; i < NPTS; i += FPS_THREADS) {
        sx[i] = frame[3 * i + 0];
        sy[i] = frame[3 * i + 1];
        sz[i] = frame[3 * i + 2];
    }
    __syncthreads();

    float prx[4], pry[4], prz[4], dist[4];
#pragma unroll
    for (int s = 0; s < 4; s++) {
        int i = tid + s * FPS_THREADS;
        prx[s] = sx[i]; pry[s] = sy[i]; prz[s] = sz[i];
        dist[s] = 1e10f;
    }

    if (tid == 0) {
        float* ap = out + (size_t)g * MANCH * 3;
        ap[0] = sx[0]; ap[1] = sy[0]; ap[2] = sz[0];
    }

    float px = sx[0], py = sy[0], pz = sz[0];

    for (int step = 1; step < MANCH; step++) {
        float bv = -1.0f;
        int   bi = NPTS;
#pragma unroll
        for (int s = 0; s < 4; s++) {
            int i = tid + s * FPS_THREADS;
            float d2 = dist2_precise(prx[s], pry[s], prz[s], px, py, pz);
            float dd = fminf(dist[s], d2);
            dist[s] = dd;
            if (dd > bv || (dd == bv && i < bi)) { bv = dd; bi = i; }
        }
#pragma unroll
        for (int off = 16; off; off >>= 1) {
            float ov = __shfl_down_sync(0xffffffffu, bv, off);
            int   oi = __shfl_down_sync(0xffffffffu, bi, off);
            if (ov > bv || (ov == bv && oi < bi)) { bv = ov; bi = oi; }
        }
        if ((tid & 31) == 0) { redV[tid >> 5] = bv; redI[tid >> 5] = bi; }
        __syncthreads();
        if (tid < 32) {
            bv = redV[tid];
            bi = redI[tid];
#pragma unroll
            for (int off = 16; off; off >>= 1) {
                float ov = __shfl_down_sync(0xffffffffu, bv, off);
                int   oi = __shfl_down_sync(0xffffffffu, bi, off);
                if (ov > bv || (ov == bv && oi < bi)) { bv = ov; bi = oi; }
            }
            if (tid == 0) {
                curP[0] = sx[bi]; curP[1] = sy[bi]; curP[2] = sz[bi];
                float* ap = out + ((size_t)g * MANCH + step) * 3;
                ap[0] = sx[bi]; ap[1] = sy[bi]; ap[2] = sz[bi];
            }
        }
        __syncthreads();
        px = curP[0]; py = curP[1]; pz = curP[2];
    }
}

// ---------------------------------------------------------------------------
// Kernel B: ball query + layer1(fp32) + layer2 on fp16 m16n8k16 tensor cores
// + max-over-k in fragments + sum-over-dt.
// Grid (8,64), block 256 = 8 warps; warp owns 2 anchors sequentially.
// Per warp: 4.25KB smem B buffer (h1 as half2 pairs, k-row stride BSTRIDE).
// ---------------------------------------------------------------------------
__global__ void __launch_bounds__(CONV_THREADS, 2) conv_kernel(
    const float* __restrict__ xyzs,
    float* __restrict__ out) {
    extern __shared__ float sm[];
    float* sx = sm;
    float* sy = sm + NPTS;
    float* sz = sm + 2 * NPTS;
    uint32_t* sB = (uint32_t*)(sm + 3 * NPTS);          // 8 warps * 32*BSTRIDE
    int* sidx = (int*)(sB + 8 * KNN * BSTRIDE);          // 8 warps * 32

    int tile = blockIdx.x, g = blockIdx.y;
    int b = g >> 4, f = g & 15;
    int tid = threadIdx.x, warp = tid >> 5, lane = tid & 31;
    int gid = lane >> 2, tig = lane & 3;
    uint32_t* wB = sB + warp * KNN * BSTRIDE;
    int* ib = sidx + warp * KNN;

    int m0 = tile * 16 + warp * 2;
    const float* ap0 = out + ((size_t)g * MANCH + m0) * 3;
    float anc[2][3];
    anc[0][0] = ap0[0]; anc[0][1] = ap0[1]; anc[0][2] = ap0[2];
    anc[1][0] = ap0[3]; anc[1][1] = ap0[4]; anc[1][2] = ap0[5];

    // accM[a][2*mt+hi] = running sum over dt of rowmax for o = mt*16+gid+8*hi
    float accM[2][16];
#pragma unroll
    for (int a = 0; a < 2; a++)
#pragma unroll
        for (int i = 0; i < 16; i++) accM[a][i] = 0.0f;

    for (int dt = -1; dt <= 1; dt++) {
        int t = 2 * f + dt;
        t = t < 0 ? 0 : (t > 31 ? 31 : t);
        const float* frame = xyzs + ((size_t)(b * 32 + t)) * NPTS * 3;
        __syncthreads();
        for (int i = tid; i < NPTS; i += CONV_THREADS) {
            sx[i] = frame[3 * i + 0];
            sy[i] = frame[3 * i + 1];
            sz[i] = frame[3 * i + 2];
        }
        __syncthreads();
        float dtf = (float)dt;

        for (int a = 0; a < 2; a++) {
            float ax = anc[a][0], ay = anc[a][1], az = anc[a][2];

            // ---- ball query (exact fp32; lane = neighbor slot k)
            int count = 0;
            for (int base = 0; base < NPTS && count < KNN; base += 32) {
                int i = base + lane;
                float d2 = dist2_precise(ax, ay, az, sx[i], sy[i], sz[i]);
                bool within = d2 < RR2;
                unsigned msk = __ballot_sync(0xffffffffu, within);
                int pos = count + __popc(msk & ((1u << lane) - 1u));
                if (within && pos < KNN) ib[pos] = i;
                count += __popc(msk);
            }
            __syncwarp();
            int myIdx = 0;
            if (count > 0) myIdx = ib[lane < count ? lane : 0];

            float dx = sx[myIdx] - ax;
            float dy = sy[myIdx] - ay;
            float dz = sz[myIdx] - az;

            // ---- layer 1 (fp32) -> half2 pairs in B buffer.
            // Lane = neighbor row k. For each kt(16 ch): write 4 STS.64, each
            // = {half2(ch,ch+1), half2(ch+8,ch+9)} at word k*BSTRIDE+kt*8+tig*2.
#pragma unroll
            for (int kt = 0; kt < 4; kt++) {
                float hv[16];
#pragma unroll
                for (int c = 0; c < 16; c++) {
                    float4 w = cWd[kt * 16 + c];
                    float v = fmaf(w.x, dx, fmaf(w.y, dy,
                              fmaf(w.z, dz, w.w * dtf)));
                    hv[c] = fmaxf(v, 0.0f);
                }
#pragma unroll
                for (int tg = 0; tg < 4; tg++) {
                    uint2 v;
                    v.x = pkh2(hv[2 * tg],     hv[2 * tg + 1]);
                    v.y = pkh2(hv[2 * tg + 8], hv[2 * tg + 9]);
                    *(uint2*)(wB + lane * BSTRIDE + kt * 8 + tg * 2) = v;
                }
            }
            __syncwarp();

            // ---- layer 2: D[128 o x 32 k] via 128 mma.m16n8k16 (fp16)
#pragma unroll 1
            for (int mt = 0; mt < 8; mt++) {
                float d[4][4];
#pragma unroll
                for (int nt = 0; nt < 4; nt++)
#pragma unroll
                    for (int r = 0; r < 4; r++) d[nt][r] = 0.0f;

#pragma unroll
                for (int kt = 0; kt < 4; kt++) {
                    uint4 afr = *(const uint4*)&gWmF16[((mt * 4 + kt) * 32 + lane) * 4];
#pragma unroll
                    for (int nt = 0; nt < 4; nt++) {
                        // lane needs neighbor col n = nt*8+gid, ch pairs tig*2 (+8)
                        uint2 bf = *(const uint2*)(wB + (nt * 8 + gid) * BSTRIDE
                                                   + kt * 8 + tig * 2);
                        mma_f16(d[nt][0], d[nt][1], d[nt][2], d[nt][3],
                                afr.x, afr.y, afr.z, afr.w, bf.x, bf.y);
                    }
                }
                // epilogue: max over k (cols), relu, accumulate over dt
                float mlo = fmaxf(d[0][0], d[0][1]);
                float mhi = fmaxf(d[0][2], d[0][3]);
#pragma unroll
                for (int nt = 1; nt < 4; nt++) {
                    mlo = fmaxf(mlo, fmaxf(d[nt][0], d[nt][1]));
                    mhi = fmaxf(mhi, fmaxf(d[nt][2], d[nt][3]));
                }
                mlo = fmaxf(mlo, __shfl_xor_sync(0xffffffffu, mlo, 1));
                mlo = fmaxf(mlo, __shfl_xor_sync(0xffffffffu, mlo, 2));
                mhi = fmaxf(mhi, __shfl_xor_sync(0xffffffffu, mhi, 1));
                mhi = fmaxf(mhi, __shfl_xor_sync(0xffffffffu, mhi, 2));
                accM[a][2 * mt]     += fmaxf(mlo, 0.0f);
                accM[a][2 * mt + 1] += fmaxf(mhi, 0.0f);
            }
            __syncwarp();  // B buffer reads done before next anchor overwrites
        }
    }

    // ---- write new_features: out[b,f,o,m]; lanes with tig==0 own the values
    float* feat = out + (size_t)GTOT * MANCH * 3;
    if (tig == 0) {
#pragma unroll
        for (int a = 0; a < 2; a++) {
            int m = m0 + a;
#pragma unroll
            for (int mt = 0; mt < 8; mt++) {
                int o_lo = mt * 16 + gid;
                feat[((size_t)g * GC1 + o_lo) * MANCH + m]     = accM[a][2 * mt];
                feat[((size_t)g * GC1 + o_lo + 8) * MANCH + m] = accM[a][2 * mt + 1];
            }
        }
    }
}

extern "C" void kernel_launch(void* const* d_in, const int* in_sizes, int n_in,
                              void* d_out, int out_size) {
    const float* xyzs = (const float*)d_in[0];
    const float* Wd   = (const float*)d_in[1];
    const float* Wm   = (const float*)d_in[2];
    float* out = (float*)d_out;

    cudaMemcpyToSymbolAsync(cWd, Wd, GC0 * 4 * sizeof(float), 0,
                            cudaMemcpyDeviceToDevice);

    size_t smA = (size_t)3 * NPTS * sizeof(float);
    size_t smB = (size_t)3 * NPTS * sizeof(float)            // points  (48K)
               + (size_t)8 * KNN * BSTRIDE * sizeof(uint32_t) // B bufs (34K)
               + (size_t)8 * KNN * sizeof(int);               // ball idx (1K)

    cudaFuncSetAttribute(fps_kernel,  cudaFuncAttributeMaxDynamicSharedMemorySize, (int)smA);
    cudaFuncSetAttribute(conv_kernel, cudaFuncAttributeMaxDynamicSharedMemorySize, (int)smB);

    prep_kernel<<<16, 256>>>(Wm);
    fps_kernel<<<GTOT, FPS_THREADS, smA>>>(xyzs, out);
    conv_kernel<<<dim3(8, GTOT), CONV_THREADS, smB>>>(xyzs, out);
}

// round 9
// speedup vs baseline: 1.2187x; 1.2187x over previous
#include <cuda_runtime.h>
#include <cuda_fp16.h>
#include <cstdint>
#include <cstddef>

#define NPTS   4096
#define MANCH  128
#define GC0    64
#define GC1    128
#define KNN    32
#define RR2    0.0225f
#define GTOT   64
#define FPS_THREADS 1024
#define FS     66    // B-fragment stride in words (64 + 2 pad, conflict control)

// Layer-1 weights (1KB — const-cache resident, warp-uniform reads)
__constant__ float4 cWd[GC0];
// Layer-2 weights as fp16x2 in m16n8k16 A-fragment layout:
// [mt(8)][kt(4)][lane(32)][r(4)]  (4096 words = 16KB, L1-resident)
__device__ uint32_t gWmF16[8 * 4 * 128];
// Ball-query output: [g][m][dt][c(3)][k(32)] fp32 displacements (9.4MB)
__device__ float gDisp[(size_t)GTOT * MANCH * 3 * 96];

// Exact (non-FMA-contracted) squared distance: discrete decisions
// (FPS argmax / radius threshold) match the JAX reference bit-for-bit.
__device__ __forceinline__ float dist2_precise(float ax, float ay, float az,
                                               float bx, float by, float bz) {
    float dx = __fsub_rn(ax, bx);
    float dy = __fsub_rn(ay, by);
    float dz = __fsub_rn(az, bz);
    return __fadd_rn(__fadd_rn(__fmul_rn(dx, dx), __fmul_rn(dy, dy)),
                     __fmul_rn(dz, dz));
}

// pack two fp32 -> fp16x2 (lo in low half)
__device__ __forceinline__ uint32_t pkh2(float lo, float hi) {
    uint32_t r;
    asm("cvt.rn.f16x2.f32 %0, %1, %2;" : "=r"(r) : "f"(hi), "f"(lo));
    return r;
}

__device__ __forceinline__ void mma_f16(float& d0, float& d1, float& d2, float& d3,
                                        uint32_t a0, uint32_t a1, uint32_t a2, uint32_t a3,
                                        uint32_t b0, uint32_t b1) {
    asm volatile(
        "mma.sync.aligned.m16n8k16.row.col.f32.f16.f16.f32 "
        "{%0,%1,%2,%3}, {%4,%5,%6,%7}, {%8,%9}, {%0,%1,%2,%3};"
        : "+f"(d0), "+f"(d1), "+f"(d2), "+f"(d3)
        : "r"(a0), "r"(a1), "r"(a2), "r"(a3), "r"(b0), "r"(b1));
}

// ---------------------------------------------------------------------------
// Prep: Wm -> fp16x2 A-fragments (m16n8k16 layout). 4096 threads, 1 word each.
// ---------------------------------------------------------------------------
__global__ void prep_kernel(const float* __restrict__ Wm) {
    int idx = blockIdx.x * blockDim.x + threadIdx.x;  // 0..4095
    int r = idx & 3;
    int l = (idx >> 2) & 31;
    int fid = idx >> 7;          // 0..31 = mt*4 + kt
    int kt = fid & 3, mt = fid >> 2;
    int gid = l >> 2, tig = l & 3;
    int row = mt * 16 + gid + (r & 1) * 8;          // o index
    int ch  = kt * 16 + tig * 2 + (r >> 1) * 8;     // channel (even)
    gWmF16[idx] = pkh2(Wm[row * GC0 + ch], Wm[row * GC0 + ch + 1]);
}

// ---------------------------------------------------------------------------
// Kernel A: furthest point sampling (exact fp32). One block per group.
// ---------------------------------------------------------------------------
__global__ void __launch_bounds__(FPS_THREADS) fps_kernel(
    const float* __restrict__ xyzs, float* __restrict__ out) {
    extern __shared__ float sm[];
    float* sx = sm;
    float* sy = sm + NPTS;
    float* sz = sm + 2 * NPTS;
    __shared__ float redV[32];
    __shared__ int   redI[32];
    __shared__ float curP[3];

    int g = blockIdx.x;
    int b = g >> 4, f = g & 15;
    int t = 2 * f;
    const float* frame = xyzs + ((size_t)(b * 32 + t)) * NPTS * 3;
    int tid = threadIdx.x;

    for (int i = tid; i < NPTS; i += FPS_THREADS) {
        sx[i] = frame[3 * i + 0];
        sy[i] = frame[3 * i + 1];
        sz[i] = frame[3 * i + 2];
    }
    __syncthreads();

    float prx[4], pry[4], prz[4], dist[4];
#pragma unroll
    for (int s = 0; s < 4; s++) {
        int i = tid + s * FPS_THREADS;
        prx[s] = sx[i]; pry[s] = sy[i]; prz[s] = sz[i];
        dist[s] = 1e10f;
    }

    if (tid == 0) {
        float* ap = out + (size_t)g * MANCH * 3;
        ap[0] = sx[0]; ap[1] = sy[0]; ap[2] = sz[0];
    }

    float px = sx[0], py = sy[0], pz = sz[0];

    for (int step = 1; step < MANCH; step++) {
        float bv = -1.0f;
        int   bi = NPTS;
#pragma unroll
        for (int s = 0; s < 4; s++) {
            int i = tid + s * FPS_THREADS;
            float d2 = dist2_precise(prx[s], pry[s], prz[s], px, py, pz);
            float dd = fminf(dist[s], d2);
            dist[s] = dd;
            if (dd > bv || (dd == bv && i < bi)) { bv = dd; bi = i; }
        }
#pragma unroll
        for (int off = 16; off; off >>= 1) {
            float ov = __shfl_down_sync(0xffffffffu, bv, off);
            int   oi = __shfl_down_sync(0xffffffffu, bi, off);
            if (ov > bv || (ov == bv && oi < bi)) { bv = ov; bi = oi; }
        }
        if ((tid & 31) == 0) { redV[tid >> 5] = bv; redI[tid >> 5] = bi; }
        __syncthreads();
        if (tid < 32) {
            bv = redV[tid];
            bi = redI[tid];
#pragma unroll
            for (int off = 16; off; off >>= 1) {
                float ov = __shfl_down_sync(0xffffffffu, bv, off);
                int   oi = __shfl_down_sync(0xffffffffu, bi, off);
                if (ov > bv || (ov == bv && oi < bi)) { bv = ov; bi = oi; }
            }
            if (tid == 0) {
                curP[0] = sx[bi]; curP[1] = sy[bi]; curP[2] = sz[bi];
                float* ap = out + ((size_t)g * MANCH + step) * 3;
                ap[0] = sx[bi]; ap[1] = sy[bi]; ap[2] = sz[bi];
            }
        }
        __syncthreads();
        px = curP[0]; py = curP[1]; pz = curP[2];
    }
}

// ---------------------------------------------------------------------------
// Kernel B1: ball query only. Grid (16,64), block 256 = 8 warps, warp = one
// anchor, loops 3 dts. ~40 regs + 49KB smem -> 4 blocks/SM = 32 warps.
// Writes fp32 displacement vectors to gDisp (coalesced).
// ---------------------------------------------------------------------------
__global__ void __launch_bounds__(256, 4) query_kernel(
    const float* __restrict__ xyzs,
    const float* __restrict__ anchors) {
    extern __shared__ float sm[];
    float* sx = sm;
    float* sy = sm + NPTS;
    float* sz = sm + 2 * NPTS;
    int* sidx = (int*)(sm + 3 * NPTS);   // 8 warps * 32

    int tile = blockIdx.x, g = blockIdx.y;
    int b = g >> 4, f = g & 15;
    int tid = threadIdx.x, warp = tid >> 5, lane = tid & 31;
    int m = tile * 8 + warp;
    int* ib = sidx + warp * KNN;

    const float* ap = anchors + ((size_t)g * MANCH + m) * 3;
    float ax = ap[0], ay = ap[1], az = ap[2];

    for (int dtI = 0; dtI < 3; dtI++) {
        int t = 2 * f + dtI - 1;
        t = t < 0 ? 0 : (t > 31 ? 31 : t);
        const float* frame = xyzs + ((size_t)(b * 32 + t)) * NPTS * 3;
        __syncthreads();
        for (int i = tid; i < NPTS; i += 256) {
            sx[i] = frame[3 * i + 0];
            sy[i] = frame[3 * i + 1];
            sz[i] = frame[3 * i + 2];
        }
        __syncthreads();

        // first-KNN-within-radius, ascending index (exact semantics)
        int count = 0;
        for (int base = 0; base < NPTS && count < KNN; base += 32) {
            int i = base + lane;
            float d2 = dist2_precise(ax, ay, az, sx[i], sy[i], sz[i]);
            bool within = d2 < RR2;
            unsigned msk = __ballot_sync(0xffffffffu, within);
            int pos = count + __popc(msk & ((1u << lane) - 1u));
            if (within && pos < KNN) ib[pos] = i;
            count += __popc(msk);
        }
        __syncwarp();
        int myIdx = 0;  // no valid neighbor -> index 0 (reference semantics)
        if (count > 0) myIdx = ib[lane < count ? lane : 0];

        float* dst = gDisp + (((size_t)g * MANCH + m) * 3 + dtI) * 96;
        dst[lane]      = sx[myIdx] - ax;
        dst[32 + lane] = sy[myIdx] - ay;
        dst[64 + lane] = sz[myIdx] - az;
    }
}

// ---------------------------------------------------------------------------
// Kernel B2: layer1 (fp32) + layer2 fp16 m16n8k16 MMA + max-over-k + sum-dt.
// Grid (16,64), block 256 = 8 warps, warp = one anchor (3 dts in sequence).
// smem: only B-fragment buffers (8 * 16*FS words = 33KB) -> high occupancy.
// ---------------------------------------------------------------------------
__global__ void __launch_bounds__(256, 3) mlp_kernel(float* __restrict__ out) {
    extern __shared__ uint32_t smB[];   // 8 warps * 16 frags * FS words
    int tile = blockIdx.x, g = blockIdx.y;
    int tid = threadIdx.x, warp = tid >> 5, lane = tid & 31;
    int gid = lane >> 2, tig = lane & 3;
    uint32_t* wB = smB + warp * 16 * FS;
    int m = tile * 8 + warp;

    // producer role: this lane is neighbor j = lane
    int ntp = lane >> 3, g8 = lane & 7;

    float accM[16];
#pragma unroll
    for (int i = 0; i < 16; i++) accM[i] = 0.0f;

    for (int dtI = 0; dtI < 3; dtI++) {
        const float* src = gDisp + (((size_t)g * MANCH + m) * 3 + dtI) * 96;
        float dx = src[lane], dy = src[32 + lane], dz = src[64 + lane];
        float dtf = (float)(dtI - 1);

        // ---- layer 1 (fp32) -> fp16 B fragments (fragment-major, FS pad)
#pragma unroll
        for (int kt = 0; kt < 4; kt++) {
            float hv[16];
#pragma unroll
            for (int c = 0; c < 16; c++) {
                float4 w = cWd[kt * 16 + c];
                float v = fmaf(w.x, dx, fmaf(w.y, dy, fmaf(w.z, dz, w.w * dtf)));
                hv[c] = fmaxf(v, 0.0f);
            }
#pragma unroll
            for (int tg = 0; tg < 4; tg++) {
                uint2 v;
                v.x = pkh2(hv[2 * tg],     hv[2 * tg + 1]);
                v.y = pkh2(hv[2 * tg + 8], hv[2 * tg + 9]);
                *(uint2*)(wB + (kt * 4 + ntp) * FS + (g8 * 4 + tg) * 2) = v;
            }
        }
        __syncwarp();

        // ---- layer 2: D[128 o x 32 k] via 128 mma.m16n8k16 (fp16)
#pragma unroll 1
        for (int mt = 0; mt < 8; mt++) {
            float d[4][4];
#pragma unroll
            for (int nt = 0; nt < 4; nt++)
#pragma unroll
                for (int r = 0; r < 4; r++) d[nt][r] = 0.0f;

#pragma unroll
            for (int kt = 0; kt < 4; kt++) {
                uint4 afr = *(const uint4*)&gWmF16[((mt * 4 + kt) * 32 + lane) * 4];
#pragma unroll
                for (int nt = 0; nt < 4; nt++) {
                    uint2 bf = *(const uint2*)(wB + (kt * 4 + nt) * FS + lane * 2);
                    mma_f16(d[nt][0], d[nt][1], d[nt][2], d[nt][3],
                            afr.x, afr.y, afr.z, afr.w, bf.x, bf.y);
                }
            }
            // epilogue: max over neighbors (cols), relu, accumulate over dt
            float mlo = fmaxf(d[0][0], d[0][1]);
            float mhi = fmaxf(d[0][2], d[0][3]);
#pragma unroll
            for (int nt = 1; nt < 4; nt++) {
                mlo = fmaxf(mlo, fmaxf(d[nt][0], d[nt][1]));
                mhi = fmaxf(mhi, fmaxf(d[nt][2], d[nt][3]));
            }
            mlo = fmaxf(mlo, __shfl_xor_sync(0xffffffffu, mlo, 1));
            mlo = fmaxf(mlo, __shfl_xor_sync(0xffffffffu, mlo, 2));
            mhi = fmaxf(mhi, __shfl_xor_sync(0xffffffffu, mhi, 1));
            mhi = fmaxf(mhi, __shfl_xor_sync(0xffffffffu, mhi, 2));
            accM[2 * mt]     += fmaxf(mlo, 0.0f);
            accM[2 * mt + 1] += fmaxf(mhi, 0.0f);
        }
        __syncwarp();  // reads done before next dt's producer overwrites
    }

    // ---- write new_features: out[b,f,o,m] after the new_xyzs block
    float* feat = out + (size_t)GTOT * MANCH * 3;
    if (tig == 0) {
#pragma unroll
        for (int mt = 0; mt < 8; mt++) {
            int o_lo = mt * 16 + gid;
            feat[((size_t)g * GC1 + o_lo) * MANCH + m]     = accM[2 * mt];
            feat[((size_t)g * GC1 + o_lo + 8) * MANCH + m] = accM[2 * mt + 1];
        }
    }
}

extern "C" void kernel_launch(void* const* d_in, const int* in_sizes, int n_in,
                              void* d_out, int out_size) {
    const float* xyzs = (const float*)d_in[0];
    const float* Wd   = (const float*)d_in[1];
    const float* Wm   = (const float*)d_in[2];
    float* out = (float*)d_out;

    cudaMemcpyToSymbolAsync(cWd, Wd, GC0 * 4 * sizeof(float), 0,
                            cudaMemcpyDeviceToDevice);

    size_t smF = (size_t)3 * NPTS * sizeof(float);                    // 48K
    size_t smQ = smF + (size_t)8 * KNN * sizeof(int);                 // 49K
    size_t smM = (size_t)8 * 16 * FS * sizeof(uint32_t);              // 33K

    cudaFuncSetAttribute(fps_kernel,   cudaFuncAttributeMaxDynamicSharedMemorySize, (int)smF);
    cudaFuncSetAttribute(query_kernel, cudaFuncAttributeMaxDynamicSharedMemorySize, (int)smQ);
    cudaFuncSetAttribute(mlp_kernel,   cudaFuncAttributeMaxDynamicSharedMemorySize, (int)smM);

    prep_kernel<<<16, 256>>>(Wm);
    fps_kernel<<<GTOT, FPS_THREADS, smF>>>(xyzs, out);
    query_kernel<<<dim3(16, GTOT), 256, smQ>>>(xyzs, out);
    mlp_kernel<<<dim3(16, GTOT), 256, smM>>>(out);
}

// round 10
// speedup vs baseline: 1.2272x; 1.0069x over previous
#include <cuda_runtime.h>
#include <cuda_fp16.h>
#include <cstdint>
#include <cstddef>

#define NPTS   4096
#define MANCH  128
#define GC0    64
#define GC1    128
#define KNN    32
#define RR2    0.0225f
#define GTOT   64
#define FPS_THREADS 1024
#define FS     66    // B-fragment stride in words (64 + 2 pad)

// Layer-1 weights (1KB — const-cache resident, warp-uniform reads)
__constant__ float4 cWd[GC0];
// Layer-2 weights as fp16x2 in m16n8k16 A-fragment layout:
// [mt(8)][kt(4)][lane(32)][r(4)]  (4096 words = 16KB, L1-resident)
__device__ uint32_t gWmF16[8 * 4 * 128];
// Ball-query output: [g][m][dt][c(3)][k(32)] fp32 displacements (9.4MB)
__device__ float gDisp[(size_t)GTOT * MANCH * 3 * 96];

// Exact (non-FMA-contracted) squared distance: discrete decisions
// (FPS argmax / radius threshold) match the JAX reference bit-for-bit.
__device__ __forceinline__ float dist2_precise(float ax, float ay, float az,
                                               float bx, float by, float bz) {
    float dx = __fsub_rn(ax, bx);
    float dy = __fsub_rn(ay, by);
    float dz = __fsub_rn(az, bz);
    return __fadd_rn(__fadd_rn(__fmul_rn(dx, dx), __fmul_rn(dy, dy)),
                     __fmul_rn(dz, dz));
}

// pack two fp32 -> fp16x2 (lo in low half)
__device__ __forceinline__ uint32_t pkh2(float lo, float hi) {
    uint32_t r;
    asm("cvt.rn.f16x2.f32 %0, %1, %2;" : "=r"(r) : "f"(hi), "f"(lo));
    return r;
}

__device__ __forceinline__ void mma_f16(float& d0, float& d1, float& d2, float& d3,
                                        uint32_t a0, uint32_t a1, uint32_t a2, uint32_t a3,
                                        uint32_t b0, uint32_t b1) {
    asm volatile(
        "mma.sync.aligned.m16n8k16.row.col.f32.f16.f16.f32 "
        "{%0,%1,%2,%3}, {%4,%5,%6,%7}, {%8,%9}, {%0,%1,%2,%3};"
        : "+f"(d0), "+f"(d1), "+f"(d2), "+f"(d3)
        : "r"(a0), "r"(a1), "r"(a2), "r"(a3), "r"(b0), "r"(b1));
}

// ---------------------------------------------------------------------------
// Prep: Wm -> fp16x2 A-fragments (m16n8k16 layout). 4096 threads, 1 word each.
// ---------------------------------------------------------------------------
__global__ void prep_kernel(const float* __restrict__ Wm) {
    int idx = blockIdx.x * blockDim.x + threadIdx.x;  // 0..4095
    int r = idx & 3;
    int l = (idx >> 2) & 31;
    int fid = idx >> 7;          // 0..31 = mt*4 + kt
    int kt = fid & 3, mt = fid >> 2;
    int gid = l >> 2, tig = l & 3;
    int row = mt * 16 + gid + (r & 1) * 8;          // o index
    int ch  = kt * 16 + tig * 2 + (r >> 1) * 8;     // channel (even)
    gWmF16[idx] = pkh2(Wm[row * GC0 + ch], Wm[row * GC0 + ch + 1]);
}

// ---------------------------------------------------------------------------
// Kernel A: furthest point sampling (exact fp32). One block per group.
// ---------------------------------------------------------------------------
__global__ void __launch_bounds__(FPS_THREADS) fps_kernel(
    const float* __restrict__ xyzs, float* __restrict__ out) {
    extern __shared__ float sm[];
    float* sx = sm;
    float* sy = sm + NPTS;
    float* sz = sm + 2 * NPTS;
    __shared__ float redV[32];
    __shared__ int   redI[32];
    __shared__ float curP[3];

    int g = blockIdx.x;
    int b = g >> 4, f = g & 15;
    int t = 2 * f;
    const float* frame = xyzs + ((size_t)(b * 32 + t)) * NPTS * 3;
    int tid = threadIdx.x;

    for (int i = tid; i < NPTS; i += FPS_THREADS) {
        sx[i] = frame[3 * i + 0];
        sy[i] = frame[3 * i + 1];
        sz[i] = frame[3 * i + 2];
    }
    __syncthreads();

    float prx[4], pry[4], prz[4], dist[4];
#pragma unroll
    for (int s = 0; s < 4; s++) {
        int i = tid + s * FPS_THREADS;
        prx[s] = sx[i]; pry[s] = sy[i]; prz[s] = sz[i];
        dist[s] = 1e10f;
    }

    if (tid == 0) {
        float* ap = out + (size_t)g * MANCH * 3;
        ap[0] = sx[0]; ap[1] = sy[0]; ap[2] = sz[0];
    }

    float px = sx[0], py = sy[0], pz = sz[0];

    for (int step = 1; step < MANCH; step++) {
        float bv = -1.0f;
        int   bi = NPTS;
#pragma unroll
        for (int s = 0; s < 4; s++) {
            int i = tid + s * FPS_THREADS;
            float d2 = dist2_precise(prx[s], pry[s], prz[s], px, py, pz);
            float dd = fminf(dist[s], d2);
            dist[s] = dd;
            if (dd > bv || (dd == bv && i < bi)) { bv = dd; bi = i; }
        }
#pragma unroll
        for (int off = 16; off; off >>= 1) {
            float ov = __shfl_down_sync(0xffffffffu, bv, off);
            int   oi = __shfl_down_sync(0xffffffffu, bi, off);
            if (ov > bv || (ov == bv && oi < bi)) { bv = ov; bi = oi; }
        }
        if ((tid & 31) == 0) { redV[tid >> 5] = bv; redI[tid >> 5] = bi; }
        __syncthreads();
        if (tid < 32) {
            bv = redV[tid];
            bi = redI[tid];
#pragma unroll
            for (int off = 16; off; off >>= 1) {
                float ov = __shfl_down_sync(0xffffffffu, bv, off);
                int   oi = __shfl_down_sync(0xffffffffu, bi, off);
                if (ov > bv || (ov == bv && oi < bi)) { bv = ov; bi = oi; }
            }
            if (tid == 0) {
                curP[0] = sx[bi]; curP[1] = sy[bi]; curP[2] = sz[bi];
                float* ap = out + ((size_t)g * MANCH + step) * 3;
                ap[0] = sx[bi]; ap[1] = sy[bi]; ap[2] = sz[bi];
            }
        }
        __syncthreads();
        px = curP[0]; py = curP[1]; pz = curP[2];
    }
}

// ---------------------------------------------------------------------------
// Kernel B1: ball query. Grid (3 dt, 64 g), block 512 = 16 warps.
// Frame loaded ONCE per block; each warp handles 8 anchors (m = warp + 16*i).
// 4-points-per-lane ballot scan: 128 points per iteration.
// ---------------------------------------------------------------------------
__global__ void __launch_bounds__(512, 2) query_kernel(
    const float* __restrict__ xyzs,
    const float* __restrict__ anchors) {
    extern __shared__ float sm[];
    float* sx = sm;
    float* sy = sm + NPTS;
    float* sz = sm + 2 * NPTS;
    int* sidx = (int*)(sm + 3 * NPTS);   // 16 warps * 32

    int dtI = blockIdx.x, g = blockIdx.y;
    int b = g >> 4, f = g & 15;
    int tid = threadIdx.x, warp = tid >> 5, lane = tid & 31;
    int* ib = sidx + warp * KNN;

    int t = 2 * f + dtI - 1;
    t = t < 0 ? 0 : (t > 31 ? 31 : t);
    const float* frame = xyzs + ((size_t)(b * 32 + t)) * NPTS * 3;
    for (int i = tid; i < NPTS; i += 512) {
        sx[i] = frame[3 * i + 0];
        sy[i] = frame[3 * i + 1];
        sz[i] = frame[3 * i + 2];
    }
    __syncthreads();

    unsigned lt = (1u << lane) - 1u;

    for (int mi = 0; mi < 8; mi++) {
        int m = warp + 16 * mi;
        const float* ap = anchors + ((size_t)g * MANCH + m) * 3;
        float ax = ap[0], ay = ap[1], az = ap[2];

        // first-KNN-within-radius, ascending index (exact semantics)
        int count = 0;
        for (int base = 0; base < NPTS && count < KNN; base += 128) {
            int i0 = base + lane * 4;
            float4 x4 = *(const float4*)&sx[i0];
            float4 y4 = *(const float4*)&sy[i0];
            float4 z4 = *(const float4*)&sz[i0];
            bool w0 = dist2_precise(ax, ay, az, x4.x, y4.x, z4.x) < RR2;
            bool w1 = dist2_precise(ax, ay, az, x4.y, y4.y, z4.y) < RR2;
            bool w2 = dist2_precise(ax, ay, az, x4.z, y4.z, z4.z) < RR2;
            bool w3 = dist2_precise(ax, ay, az, x4.w, y4.w, z4.w) < RR2;
            unsigned m0 = __ballot_sync(0xffffffffu, w0);
            unsigned m1 = __ballot_sync(0xffffffffu, w1);
            unsigned m2 = __ballot_sync(0xffffffffu, w2);
            unsigned m3 = __ballot_sync(0xffffffffu, w3);
            int r = count + __popc(m0 & lt) + __popc(m1 & lt)
                          + __popc(m2 & lt) + __popc(m3 & lt);
            if (w0) { if (r < KNN) ib[r] = i0;     r++; }
            if (w1) { if (r < KNN) ib[r] = i0 + 1; r++; }
            if (w2) { if (r < KNN) ib[r] = i0 + 2; r++; }
            if (w3) { if (r < KNN) ib[r] = i0 + 3; r++; }
            count += __popc(m0) + __popc(m1) + __popc(m2) + __popc(m3);
        }
        __syncwarp();
        int myIdx = 0;  // no valid neighbor -> index 0 (reference semantics)
        if (count > 0) myIdx = ib[lane < count ? lane : 0];

        float* dst = gDisp + (((size_t)g * MANCH + m) * 3 + dtI) * 96;
        dst[lane]      = sx[myIdx] - ax;
        dst[32 + lane] = sy[myIdx] - ay;
        dst[64 + lane] = sz[myIdx] - az;
        __syncwarp();
    }
}

// ---------------------------------------------------------------------------
// Kernel B2: layer1 (fp32) + layer2 fp16 m16n8k16 MMA + max-over-k + sum-dt.
// Grid (16,64), block 256 = 8 warps, warp = one anchor (3 dts in sequence).
// B fragments hoisted to registers -> only 16 consumer LDS.64 per dt.
// ---------------------------------------------------------------------------
__global__ void __launch_bounds__(256, 2) mlp_kernel(float* __restrict__ out) {
    extern __shared__ uint32_t smB[];   // 8 warps * 16 frags * FS words
    int tile = blockIdx.x, g = blockIdx.y;
    int tid = threadIdx.x, warp = tid >> 5, lane = tid & 31;
    int gid = lane >> 2, tig = lane & 3;
    uint32_t* wB = smB + warp * 16 * FS;
    int m = tile * 8 + warp;

    // producer role: this lane is neighbor j = lane
    int ntp = lane >> 3, g8 = lane & 7;

    float accM[16];
#pragma unroll
    for (int i = 0; i < 16; i++) accM[i] = 0.0f;

    for (int dtI = 0; dtI < 3; dtI++) {
        const float* src = gDisp + (((size_t)g * MANCH + m) * 3 + dtI) * 96;
        float dx = src[lane], dy = src[32 + lane], dz = src[64 + lane];
        float dtf = (float)(dtI - 1);

        // ---- layer 1 (fp32) -> fp16 B fragments (fragment-major, FS pad)
#pragma unroll
        for (int kt = 0; kt < 4; kt++) {
            float hv[16];
#pragma unroll
            for (int c = 0; c < 16; c++) {
                float4 w = cWd[kt * 16 + c];
                float v = fmaf(w.x, dx, fmaf(w.y, dy, fmaf(w.z, dz, w.w * dtf)));
                hv[c] = fmaxf(v, 0.0f);
            }
#pragma unroll
            for (int tg = 0; tg < 4; tg++) {
                uint2 v;
                v.x = pkh2(hv[2 * tg],     hv[2 * tg + 1]);
                v.y = pkh2(hv[2 * tg + 8], hv[2 * tg + 9]);
                *(uint2*)(wB + (kt * 4 + ntp) * FS + (g8 * 4 + tg) * 2) = v;
            }
        }
        __syncwarp();

        // ---- hoist all 16 B fragments to registers (one LDS.64 each)
        uint2 breg[4][4];
#pragma unroll
        for (int kt = 0; kt < 4; kt++)
#pragma unroll
            for (int nt = 0; nt < 4; nt++)
                breg[kt][nt] = *(const uint2*)(wB + (kt * 4 + nt) * FS + lane * 2);
        __syncwarp();

        // ---- layer 2: D[128 o x 32 k] via 128 mma.m16n8k16 (fp16)
#pragma unroll 1
        for (int mt = 0; mt < 8; mt++) {
            float d[4][4];
#pragma unroll
            for (int nt = 0; nt < 4; nt++)
#pragma unroll
                for (int r = 0; r < 4; r++) d[nt][r] = 0.0f;

#pragma unroll
            for (int kt = 0; kt < 4; kt++) {
                uint4 afr = *(const uint4*)&gWmF16[((mt * 4 + kt) * 32 + lane) * 4];
#pragma unroll
                for (int nt = 0; nt < 4; nt++) {
                    mma_f16(d[nt][0], d[nt][1], d[nt][2], d[nt][3],
                            afr.x, afr.y, afr.z, afr.w,
                            breg[kt][nt].x, breg[kt][nt].y);
                }
            }
            // epilogue: max over neighbors (cols), relu, accumulate over dt
            float mlo = fmaxf(d[0][0], d[0][1]);
            float mhi = fmaxf(d[0][2], d[0][3]);
#pragma unroll
            for (int nt = 1; nt < 4; nt++) {
                mlo = fmaxf(mlo, fmaxf(d[nt][0], d[nt][1]));
                mhi = fmaxf(mhi, fmaxf(d[nt][2], d[nt][3]));
            }
            mlo = fmaxf(mlo, __shfl_xor_sync(0xffffffffu, mlo, 1));
            mlo = fmaxf(mlo, __shfl_xor_sync(0xffffffffu, mlo, 2));
            mhi = fmaxf(mhi, __shfl_xor_sync(0xffffffffu, mhi, 1));
            mhi = fmaxf(mhi, __shfl_xor_sync(0xffffffffu, mhi, 2));
            accM[2 * mt]     += fmaxf(mlo, 0.0f);
            accM[2 * mt + 1] += fmaxf(mhi, 0.0f);
        }
    }

    // ---- write new_features: out[b,f,o,m] after the new_xyzs block
    float* feat = out + (size_t)GTOT * MANCH * 3;
    if (tig == 0) {
#pragma unroll
        for (int mt = 0; mt < 8; mt++) {
            int o_lo = mt * 16 + gid;
            feat[((size_t)g * GC1 + o_lo) * MANCH + m]     = accM[2 * mt];
            feat[((size_t)g * GC1 + o_lo + 8) * MANCH + m] = accM[2 * mt + 1];
        }
    }
}

extern "C" void kernel_launch(void* const* d_in, const int* in_sizes, int n_in,
                              void* d_out, int out_size) {
    const float* xyzs = (const float*)d_in[0];
    const float* Wd   = (const float*)d_in[1];
    const float* Wm   = (const float*)d_in[2];
    float* out = (float*)d_out;

    cudaMemcpyToSymbolAsync(cWd, Wd, GC0 * 4 * sizeof(float), 0,
                            cudaMemcpyDeviceToDevice);

    size_t smF = (size_t)3 * NPTS * sizeof(float);                    // 48K
    size_t smQ = smF + (size_t)16 * KNN * sizeof(int);                // 50K
    size_t smM = (size_t)8 * 16 * FS * sizeof(uint32_t);              // 33K

    cudaFuncSetAttribute(fps_kernel,   cudaFuncAttributeMaxDynamicSharedMemorySize, (int)smF);
    cudaFuncSetAttribute(query_kernel, cudaFuncAttributeMaxDynamicSharedMemorySize, (int)smQ);
    cudaFuncSetAttribute(mlp_kernel,   cudaFuncAttributeMaxDynamicSharedMemorySize, (int)smM);

    prep_kernel<<<16, 256>>>(Wm);
    fps_kernel<<<GTOT, FPS_THREADS, smF>>>(xyzs, out);
    query_kernel<<<dim3(3, GTOT), 512, smQ>>>(xyzs, out);
    mlp_kernel<<<dim3(16, GTOT), 256, smM>>>(out);
}

// round 11
// speedup vs baseline: 1.6467x; 1.3419x over previous
#include <cuda_runtime.h>
#include <cuda_fp16.h>
#include <cstdint>
#include <cstddef>

#define NPTS   4096
#define MANCH  128
#define GC0    64
#define GC1    128
#define KNN    32
#define RR2    0.0225f
#define GTOT   64
#define FPS_THREADS 1024
#define FS     66    // B-fragment stride in words (64 + 2 pad)

// Layer-1 weights (1KB — const-cache resident, warp-uniform reads)
__constant__ float4 cWd[GC0];
// Layer-2 weights as fp16x2 in m16n8k16 A-fragment layout:
// [mt(8)][kt(4)][lane(32)][r(4)]  (4096 words = 16KB, L1-resident)
__device__ uint32_t gWmF16[8 * 4 * 128];
// Ball-query output: [g][m][dt][c(3)][k(32)] fp32 displacements (9.4MB)
__device__ float gDisp[(size_t)GTOT * MANCH * 3 * 96];

// Exact (non-FMA-contracted) squared distance: discrete decisions
// (FPS argmax / radius threshold) match the JAX reference bit-for-bit.
__device__ __forceinline__ float dist2_precise(float ax, float ay, float az,
                                               float bx, float by, float bz) {
    float dx = __fsub_rn(ax, bx);
    float dy = __fsub_rn(ay, by);
    float dz = __fsub_rn(az, bz);
    return __fadd_rn(__fadd_rn(__fmul_rn(dx, dx), __fmul_rn(dy, dy)),
                     __fmul_rn(dz, dz));
}

__device__ __forceinline__ unsigned redux_max_u32(unsigned v) {
    unsigned r;
    asm("redux.sync.max.u32 %0, %1, 0xffffffff;" : "=r"(r) : "r"(v));
    return r;
}
__device__ __forceinline__ unsigned redux_min_u32(unsigned v) {
    unsigned r;
    asm("redux.sync.min.u32 %0, %1, 0xffffffff;" : "=r"(r) : "r"(v));
    return r;
}

// pack two fp32 -> fp16x2 (lo in low half)
__device__ __forceinline__ uint32_t pkh2(float lo, float hi) {
    uint32_t r;
    asm("cvt.rn.f16x2.f32 %0, %1, %2;" : "=r"(r) : "f"(hi), "f"(lo));
    return r;
}

__device__ __forceinline__ void mma_f16(float& d0, float& d1, float& d2, float& d3,
                                        uint32_t a0, uint32_t a1, uint32_t a2, uint32_t a3,
                                        uint32_t b0, uint32_t b1) {
    asm volatile(
        "mma.sync.aligned.m16n8k16.row.col.f32.f16.f16.f32 "
        "{%0,%1,%2,%3}, {%4,%5,%6,%7}, {%8,%9}, {%0,%1,%2,%3};"
        : "+f"(d0), "+f"(d1), "+f"(d2), "+f"(d3)
        : "r"(a0), "r"(a1), "r"(a2), "r"(a3), "r"(b0), "r"(b1));
}

// ---------------------------------------------------------------------------
// Kernel A: FPS (blocks 0..63) + Wm fragment prep (blocks 64..67).
// FPS: 1 BAR per step; warp argmax via redux.max (dist>=0 so u32-order = fp
// order) + redux.min on candidate indices for exact first-occurrence ties.
// ---------------------------------------------------------------------------
__global__ void __launch_bounds__(FPS_THREADS) fps_kernel(
    const float* __restrict__ xyzs, const float* __restrict__ Wm,
    float* __restrict__ out) {
    if (blockIdx.x >= GTOT) {
        // ---- prep: Wm -> fp16x2 m16n8k16 A-fragments
        int idx = (blockIdx.x - GTOT) * FPS_THREADS + threadIdx.x;  // 0..4095
        int r = idx & 3;
        int l = (idx >> 2) & 31;
        int fid = idx >> 7;
        int kt = fid & 3, mt = fid >> 2;
        int gid = l >> 2, tig = l & 3;
        int row = mt * 16 + gid + (r & 1) * 8;
        int ch  = kt * 16 + tig * 2 + (r >> 1) * 8;
        gWmF16[idx] = pkh2(Wm[row * GC0 + ch], Wm[row * GC0 + ch + 1]);
        return;
    }

    extern __shared__ float sm[];
    float* sx = sm;
    float* sy = sm + NPTS;
    float* sz = sm + 2 * NPTS;
    __shared__ float redV[2][32];
    __shared__ int   redI[2][32];

    int g = blockIdx.x;
    int b = g >> 4, f = g & 15;
    int t = 2 * f;
    const float* frame = xyzs + ((size_t)(b * 32 + t)) * NPTS * 3;
    int tid = threadIdx.x, lane = tid & 31, wid = tid >> 5;

    for (int i = tid; i < NPTS; i += FPS_THREADS) {
        sx[i] = frame[3 * i + 0];
        sy[i] = frame[3 * i + 1];
        sz[i] = frame[3 * i + 2];
    }
    __syncthreads();

    float prx[4], pry[4], prz[4], dist[4];
#pragma unroll
    for (int s = 0; s < 4; s++) {
        int i = tid + s * FPS_THREADS;
        prx[s] = sx[i]; pry[s] = sy[i]; prz[s] = sz[i];
        dist[s] = 1e10f;
    }

    if (tid == 0) {
        float* ap = out + (size_t)g * MANCH * 3;
        ap[0] = sx[0]; ap[1] = sy[0]; ap[2] = sz[0];
    }

    float px = sx[0], py = sy[0], pz = sz[0];

    for (int step = 1; step < MANCH; step++) {
        int par = step & 1;
        float bv = -1.0f;
        int   bi = 0x7FFFFFFF;
#pragma unroll
        for (int s = 0; s < 4; s++) {   // s ascending => smallest i kept on ties
            int i = tid + s * FPS_THREADS;
            float d2 = dist2_precise(prx[s], pry[s], prz[s], px, py, pz);
            float dd = fminf(dist[s], d2);
            dist[s] = dd;
            if (dd > bv) { bv = dd; bi = i; }
        }
        // warp argmax: dd >= 0 so u32 bit order == fp order; exact ties share
        // identical bit patterns, redux.min picks the smallest index.
        unsigned wm = redux_max_u32(__float_as_uint(bv));
        unsigned ci = (__float_as_uint(bv) == wm) ? (unsigned)bi : 0x7FFFFFFFu;
        unsigned wi = redux_min_u32(ci);
        if (lane == 0) { redV[par][wid] = __uint_as_float(wm); redI[par][wid] = (int)wi; }
        __syncthreads();
        // every warp reduces the 32 partials itself (no second barrier;
        // parity double-buffer keeps step k+1 writes off step k's buffer)
        float    v  = redV[par][lane];
        unsigned ix = (unsigned)redI[par][lane];
        unsigned gmx = redux_max_u32(__float_as_uint(v));
        unsigned ci2 = (__float_as_uint(v) == gmx) ? ix : 0x7FFFFFFFu;
        int gi = (int)redux_min_u32(ci2);
        px = sx[gi]; py = sy[gi]; pz = sz[gi];
        if (tid == 0) {
            float* ap = out + ((size_t)g * MANCH + step) * 3;
            ap[0] = px; ap[1] = py; ap[2] = pz;
        }
    }
}

// ---------------------------------------------------------------------------
// Kernel B1: ball query. Grid (3 dt, 64 g, 2 half), block 256 = 8 warps.
// 4 blocks/SM -> all 384 blocks resident in ONE wave. Frame loaded once per
// block; warp handles 8 anchors via 4-points-per-lane ballot scan.
// ---------------------------------------------------------------------------
__global__ void __launch_bounds__(256, 4) query_kernel(
    const float* __restrict__ xyzs,
    const float* __restrict__ anchors) {
    extern __shared__ float sm[];
    float* sx = sm;
    float* sy = sm + NPTS;
    float* sz = sm + 2 * NPTS;
    int* sidx = (int*)(sm + 3 * NPTS);   // 8 warps * 32

    int dtI = blockIdx.x, g = blockIdx.y, half = blockIdx.z;
    int b = g >> 4, f = g & 15;
    int tid = threadIdx.x, warp = tid >> 5, lane = tid & 31;
    int* ib = sidx + warp * KNN;

    int t = 2 * f + dtI - 1;
    t = t < 0 ? 0 : (t > 31 ? 31 : t);
    const float* frame = xyzs + ((size_t)(b * 32 + t)) * NPTS * 3;
    for (int i = tid; i < NPTS; i += 256) {
        sx[i] = frame[3 * i + 0];
        sy[i] = frame[3 * i + 1];
        sz[i] = frame[3 * i + 2];
    }
    __syncthreads();

    unsigned lt = (1u << lane) - 1u;

    for (int mi = 0; mi < 8; mi++) {
        int m = half * 64 + mi * 8 + warp;
        const float* ap = anchors + ((size_t)g * MANCH + m) * 3;
        float ax = ap[0], ay = ap[1], az = ap[2];

        // first-KNN-within-radius, ascending index (exact semantics)
        int count = 0;
        for (int base = 0; base < NPTS && count < KNN; base += 128) {
            int i0 = base + lane * 4;
            float4 x4 = *(const float4*)&sx[i0];
            float4 y4 = *(const float4*)&sy[i0];
            float4 z4 = *(const float4*)&sz[i0];
            bool w0 = dist2_precise(ax, ay, az, x4.x, y4.x, z4.x) < RR2;
            bool w1 = dist2_precise(ax, ay, az, x4.y, y4.y, z4.y) < RR2;
            bool w2 = dist2_precise(ax, ay, az, x4.z, y4.z, z4.z) < RR2;
            bool w3 = dist2_precise(ax, ay, az, x4.w, y4.w, z4.w) < RR2;
            unsigned m0 = __ballot_sync(0xffffffffu, w0);
            unsigned m1 = __ballot_sync(0xffffffffu, w1);
            unsigned m2 = __ballot_sync(0xffffffffu, w2);
            unsigned m3 = __ballot_sync(0xffffffffu, w3);
            int r = count + __popc(m0 & lt) + __popc(m1 & lt)
                          + __popc(m2 & lt) + __popc(m3 & lt);
            if (w0) { if (r < KNN) ib[r] = i0;     r++; }
            if (w1) { if (r < KNN) ib[r] = i0 + 1; r++; }
            if (w2) { if (r < KNN) ib[r] = i0 + 2; r++; }
            if (w3) { if (r < KNN) ib[r] = i0 + 3; r++; }
            count += __popc(m0) + __popc(m1) + __popc(m2) + __popc(m3);
        }
        __syncwarp();
        int myIdx = 0;  // no valid neighbor -> index 0 (reference semantics)
        if (count > 0) myIdx = ib[lane < count ? lane : 0];

        float* dst = gDisp + (((size_t)g * MANCH + m) * 3 + dtI) * 96;
        dst[lane]      = sx[myIdx] - ax;
        dst[32 + lane] = sy[myIdx] - ay;
        dst[64 + lane] = sz[myIdx] - az;
        __syncwarp();
    }
}

// ---------------------------------------------------------------------------
// Kernel B2: layer1 (fp32) + layer2 fp16 m16n8k16 MMA + max-over-k + sum-dt.
// Grid (16,64), block 256 = 8 warps, warp = one anchor (3 dts in sequence).
// (R8 form: B fragments re-read from smem per mt — best measured variant.)
// ---------------------------------------------------------------------------
__global__ void __launch_bounds__(256, 3) mlp_kernel(float* __restrict__ out) {
    extern __shared__ uint32_t smB[];   // 8 warps * 16 frags * FS words
    int tile = blockIdx.x, g = blockIdx.y;
    int tid = threadIdx.x, warp = tid >> 5, lane = tid & 31;
    int gid = lane >> 2, tig = lane & 3;
    uint32_t* wB = smB + warp * 16 * FS;
    int m = tile * 8 + warp;

    // producer role: this lane is neighbor j = lane
    int ntp = lane >> 3, g8 = lane & 7;

    float accM[16];
#pragma unroll
    for (int i = 0; i < 16; i++) accM[i] = 0.0f;

    for (int dtI = 0; dtI < 3; dtI++) {
        const float* src = gDisp + (((size_t)g * MANCH + m) * 3 + dtI) * 96;
        float dx = src[lane], dy = src[32 + lane], dz = src[64 + lane];
        float dtf = (float)(dtI - 1);

        // ---- layer 1 (fp32) -> fp16 B fragments (fragment-major, FS pad)
#pragma unroll
        for (int kt = 0; kt < 4; kt++) {
            float hv[16];
#pragma unroll
            for (int c = 0; c < 16; c++) {
                float4 w = cWd[kt * 16 + c];
                float v = fmaf(w.x, dx, fmaf(w.y, dy, fmaf(w.z, dz, w.w * dtf)));
                hv[c] = fmaxf(v, 0.0f);
            }
#pragma unroll
            for (int tg = 0; tg < 4; tg++) {
                uint2 v;
                v.x = pkh2(hv[2 * tg],     hv[2 * tg + 1]);
                v.y = pkh2(hv[2 * tg + 8], hv[2 * tg + 9]);
                *(uint2*)(wB + (kt * 4 + ntp) * FS + (g8 * 4 + tg) * 2) = v;
            }
        }
        __syncwarp();

        // ---- layer 2: D[128 o x 32 k] via 128 mma.m16n8k16 (fp16)
#pragma unroll 1
        for (int mt = 0; mt < 8; mt++) {
            float d[4][4];
#pragma unroll
            for (int nt = 0; nt < 4; nt++)
#pragma unroll
                for (int r = 0; r < 4; r++) d[nt][r] = 0.0f;

#pragma unroll
            for (int kt = 0; kt < 4; kt++) {
                uint4 afr = *(const uint4*)&gWmF16[((mt * 4 + kt) * 32 + lane) * 4];
#pragma unroll
                for (int nt = 0; nt < 4; nt++) {
                    uint2 bf = *(const uint2*)(wB + (kt * 4 + nt) * FS + lane * 2);
                    mma_f16(d[nt][0], d[nt][1], d[nt][2], d[nt][3],
                            afr.x, afr.y, afr.z, afr.w, bf.x, bf.y);
                }
            }
            // epilogue: max over neighbors (cols), relu, accumulate over dt
            float mlo = fmaxf(d[0][0], d[0][1]);
            float mhi = fmaxf(d[0][2], d[0][3]);
#pragma unroll
            for (int nt = 1; nt < 4; nt++) {
                mlo = fmaxf(mlo, fmaxf(d[nt][0], d[nt][1]));
                mhi = fmaxf(mhi, fmaxf(d[nt][2], d[nt][3]));
            }
            mlo = fmaxf(mlo, __shfl_xor_sync(0xffffffffu, mlo, 1));
            mlo = fmaxf(mlo, __shfl_xor_sync(0xffffffffu, mlo, 2));
            mhi = fmaxf(mhi, __shfl_xor_sync(0xffffffffu, mhi, 1));
            mhi = fmaxf(mhi, __shfl_xor_sync(0xffffffffu, mhi, 2));
            accM[2 * mt]     += fmaxf(mlo, 0.0f);
            accM[2 * mt + 1] += fmaxf(mhi, 0.0f);
        }
        __syncwarp();  // reads done before next dt's producer overwrites
    }

    // ---- write new_features: out[b,f,o,m] after the new_xyzs block
    float* feat = out + (size_t)GTOT * MANCH * 3;
    if (tig == 0) {
#pragma unroll
        for (int mt = 0; mt < 8; mt++) {
            int o_lo = mt * 16 + gid;
            feat[((size_t)g * GC1 + o_lo) * MANCH + m]     = accM[2 * mt];
            feat[((size_t)g * GC1 + o_lo + 8) * MANCH + m] = accM[2 * mt + 1];
        }
    }
}

extern "C" void kernel_launch(void* const* d_in, const int* in_sizes, int n_in,
                              void* d_out, int out_size) {
    const float* xyzs = (const float*)d_in[0];
    const float* Wd   = (const float*)d_in[1];
    const float* Wm   = (const float*)d_in[2];
    float* out = (float*)d_out;

    cudaMemcpyToSymbolAsync(cWd, Wd, GC0 * 4 * sizeof(float), 0,
                            cudaMemcpyDeviceToDevice);

    size_t smF = (size_t)3 * NPTS * sizeof(float);                    // 48K
    size_t smQ = smF + (size_t)8 * KNN * sizeof(int);                 // 49K
    size_t smM = (size_t)8 * 16 * FS * sizeof(uint32_t);              // 33K

    cudaFuncSetAttribute(fps_kernel,   cudaFuncAttributeMaxDynamicSharedMemorySize, (int)smF);
    cudaFuncSetAttribute(query_kernel, cudaFuncAttributeMaxDynamicSharedMemorySize, (int)smQ);
    cudaFuncSetAttribute(mlp_kernel,   cudaFuncAttributeMaxDynamicSharedMemorySize, (int)smM);

    fps_kernel<<<GTOT + 4, FPS_THREADS, smF>>>(xyzs, Wm, out);   // fps + prep
    query_kernel<<<dim3(3, GTOT, 2), 256, smQ>>>(xyzs, out);
    mlp_kernel<<<dim3(16, GTOT), 256, smM>>>(out);
}

// round 13
// speedup vs baseline: 1.7333x; 1.0526x over previous
#include <cuda_runtime.h>
#include <cuda_fp16.h>
#include <cstdint>
#include <cstddef>

#define NPTS   4096
#define MANCH  128
#define GC0    64
#define GC1    128
#define KNN    32
#define RR2    0.0225f
#define GTOT   64
#define FPS_THREADS 1024
#define FS     66    // B-fragment stride in words (64 + 2 pad)

// Layer-1 weights (1KB — const-cache resident, warp-uniform reads)
__constant__ float4 cWd[GC0];
// Layer-2 weights as fp16x2 in m16n8k16 A-fragment layout:
// [mt(8)][kt(4)][lane(32)][r(4)]  (4096 words = 16KB, L1-resident)
__device__ uint32_t gWmF16[8 * 4 * 128];
// Ball-query output: [g][m][dt][c(3)][k(32)] fp32 displacements (9.4MB)
__device__ float gDisp[(size_t)GTOT * MANCH * 3 * 96];

// Exact (non-FMA-contracted) squared distance: discrete decisions
// (radius threshold) match the JAX reference bit-for-bit.
__device__ __forceinline__ float dist2_precise(float ax, float ay, float az,
                                               float bx, float by, float bz) {
    float dx = __fsub_rn(ax, bx);
    float dy = __fsub_rn(ay, by);
    float dz = __fsub_rn(az, bz);
    return __fadd_rn(__fadd_rn(__fmul_rn(dx, dx), __fmul_rn(dy, dy)),
                     __fmul_rn(dz, dz));
}

// ---- packed f32x2 helpers (per-lane rounding identical to scalar ops) ----
typedef unsigned long long u64t;
__device__ __forceinline__ u64t pk2f(float lo, float hi) {
    u64t r; asm("mov.b64 %0, {%1, %2};" : "=l"(r) : "f"(lo), "f"(hi)); return r;
}
__device__ __forceinline__ void upk2f(float& lo, float& hi, u64t v) {
    asm("mov.b64 {%0, %1}, %2;" : "=f"(lo), "=f"(hi) : "l"(v));
}
__device__ __forceinline__ u64t sub2(u64t a, u64t b) {
    u64t d; asm("sub.rn.f32x2 %0, %1, %2;" : "=l"(d) : "l"(a), "l"(b)); return d;
}
__device__ __forceinline__ u64t mul2(u64t a, u64t b) {
    u64t d; asm("mul.rn.f32x2 %0, %1, %2;" : "=l"(d) : "l"(a), "l"(b)); return d;
}
__device__ __forceinline__ u64t add2(u64t a, u64t b) {
    u64t d; asm("add.rn.f32x2 %0, %1, %2;" : "=l"(d) : "l"(a), "l"(b)); return d;
}

__device__ __forceinline__ unsigned redux_max_u32(unsigned v) {
    unsigned r;
    asm("redux.sync.max.u32 %0, %1, 0xffffffff;" : "=r"(r) : "r"(v));
    return r;
}
__device__ __forceinline__ unsigned redux_min_u32(unsigned v) {
    unsigned r;
    asm("redux.sync.min.u32 %0, %1, 0xffffffff;" : "=r"(r) : "r"(v));
    return r;
}

// pack two fp32 -> fp16x2 (lo in low half)
__device__ __forceinline__ uint32_t pkh2(float lo, float hi) {
    uint32_t r;
    asm("cvt.rn.f16x2.f32 %0, %1, %2;" : "=r"(r) : "f"(hi), "f"(lo));
    return r;
}

__device__ __forceinline__ void mma_f16(float& d0, float& d1, float& d2, float& d3,
                                        uint32_t a0, uint32_t a1, uint32_t a2, uint32_t a3,
                                        uint32_t b0, uint32_t b1) {
    asm volatile(
        "mma.sync.aligned.m16n8k16.row.col.f32.f16.f16.f32 "
        "{%0,%1,%2,%3}, {%4,%5,%6,%7}, {%8,%9}, {%0,%1,%2,%3};"
        : "+f"(d0), "+f"(d1), "+f"(d2), "+f"(d3)
        : "r"(a0), "r"(a1), "r"(a2), "r"(a3), "r"(b0), "r"(b1));
}

// ---------------------------------------------------------------------------
// Kernel A: FPS (blocks 0..63) + Wm fragment prep (blocks 64..67).
// Packed f32x2 distance arithmetic (bit-exact per lane); scalar min/max
// bookkeeping; deferred argmax index recovery in ascending order so
// first-occurrence ties match jnp.argmax exactly.
// ---------------------------------------------------------------------------
__global__ void __launch_bounds__(FPS_THREADS) fps_kernel(
    const float* __restrict__ xyzs, const float* __restrict__ Wm,
    float* __restrict__ out) {
    if (blockIdx.x >= GTOT) {
        // ---- prep: Wm -> fp16x2 m16n8k16 A-fragments
        int idx = (blockIdx.x - GTOT) * FPS_THREADS + threadIdx.x;  // 0..4095
        int r = idx & 3;
        int l = (idx >> 2) & 31;
        int fid = idx >> 7;
        int kt = fid & 3, mt = fid >> 2;
        int gid = l >> 2, tig = l & 3;
        int row = mt * 16 + gid + (r & 1) * 8;
        int ch  = kt * 16 + tig * 2 + (r >> 1) * 8;
        gWmF16[idx] = pkh2(Wm[row * GC0 + ch], Wm[row * GC0 + ch + 1]);
        return;
    }

    extern __shared__ float sm[];
    float* sx = sm;
    float* sy = sm + NPTS;
    float* sz = sm + 2 * NPTS;
    __shared__ float redV[2][32];
    __shared__ int   redI[2][32];

    int g = blockIdx.x;
    int b = g >> 4, f = g & 15;
    int t = 2 * f;
    const float* frame = xyzs + ((size_t)(b * 32 + t)) * NPTS * 3;
    int tid = threadIdx.x, lane = tid & 31, wid = tid >> 5;

    for (int i = tid; i < NPTS; i += FPS_THREADS) {
        sx[i] = frame[3 * i + 0];
        sy[i] = frame[3 * i + 1];
        sz[i] = frame[3 * i + 2];
    }
    __syncthreads();

    // lane's 4 points packed: pair p holds (i = tid + 2p*1024, i + 1024)
    u64t X2[2], Y2[2], Z2[2];
    float dist[4];
#pragma unroll
    for (int p = 0; p < 2; p++) {
        int i0 = tid + 2 * p * FPS_THREADS;
        X2[p] = pk2f(sx[i0], sx[i0 + FPS_THREADS]);
        Y2[p] = pk2f(sy[i0], sy[i0 + FPS_THREADS]);
        Z2[p] = pk2f(sz[i0], sz[i0 + FPS_THREADS]);
    }
#pragma unroll
    for (int s = 0; s < 4; s++) dist[s] = 1e10f;

    if (tid == 0) {
        float* ap = out + (size_t)g * MANCH * 3;
        ap[0] = sx[0]; ap[1] = sy[0]; ap[2] = sz[0];
    }

    float px = sx[0], py = sy[0], pz = sz[0];

    for (int step = 1; step < MANCH; step++) {
        int par = step & 1;
        u64t pxx = pk2f(px, px), pyy = pk2f(py, py), pzz = pk2f(pz, pz);
        // packed exact distance: per packed lane = sub, mul, add, add (rn)
        float nd[4];
#pragma unroll
        for (int p = 0; p < 2; p++) {
            u64t dx = sub2(X2[p], pxx);
            u64t dy = sub2(Y2[p], pyy);
            u64t dz = sub2(Z2[p], pzz);
            u64t d2 = add2(add2(mul2(dx, dx), mul2(dy, dy)), mul2(dz, dz));
            upk2f(nd[2 * p], nd[2 * p + 1], d2);
        }
        // scalar min-update + max tracking (same semantics as reference)
        float bv = -1.0f;
#pragma unroll
        for (int s = 0; s < 4; s++) {
            dist[s] = fminf(dist[s], (s & 1) ? nd[(s >> 1) * 2 + 1]
                                             : nd[(s >> 1) * 2]);
        }
        // NOTE: dist[] maps s -> point index tid + s*FPS_THREADS with
        // nd ordering nd[0]=i0, nd[1]=i0+1024, nd[2]=i0+2048, nd[3]=i0+3072
        dist[0] = dist[0]; // s order: 0->nd[0],1->nd[1],2->nd[2],3->nd[3]
#pragma unroll
        for (int s = 0; s < 4; s++) bv = fmaxf(bv, dist[s]);
        // warp max: values >= 0 so u32 bit order == fp order
        unsigned wm = redux_max_u32(__float_as_uint(bv));
        // deferred index recovery: first (smallest-i) dist bit-equal to wm
        unsigned ci = 0x7FFFFFFFu;
        if (__float_as_uint(dist[3]) == wm) ci = (unsigned)(tid + 3 * FPS_THREADS);
        if (__float_as_uint(dist[2]) == wm) ci = (unsigned)(tid + 2 * FPS_THREADS);
        if (__float_as_uint(dist[1]) == wm) ci = (unsigned)(tid + FPS_THREADS);
        if (__float_as_uint(dist[0]) == wm) ci = (unsigned)tid;
        unsigned wi = redux_min_u32(ci);
        if (lane == 0) { redV[par][wid] = __uint_as_float(wm); redI[par][wid] = (int)wi; }
        __syncthreads();
        // every warp reduces the 32 partials itself (parity double-buffer)
        float    v  = redV[par][lane];
        unsigned ix = (unsigned)redI[par][lane];
        unsigned gmx = redux_max_u32(__float_as_uint(v));
        unsigned ci2 = (__float_as_uint(v) == gmx) ? ix : 0x7FFFFFFFu;
        int gi = (int)redux_min_u32(ci2);
        px = sx[gi]; py = sy[gi]; pz = sz[gi];
        if (tid == 0) {
            float* ap = out + ((size_t)g * MANCH + step) * 3;
            ap[0] = px; ap[1] = py; ap[2] = pz;
        }
    }
}

// ---------------------------------------------------------------------------
// Kernel B1: ball query. Grid (3 dt, 64 g, 2 half), block 256 = 8 warps.
// 4 blocks/SM -> all 384 blocks resident in ONE wave. Frame loaded once per
// block; warp handles 8 anchors via 4-points-per-lane ballot scan.
// ---------------------------------------------------------------------------
__global__ void __launch_bounds__(256, 4) query_kernel(
    const float* __restrict__ xyzs,
    const float* __restrict__ anchors) {
    extern __shared__ float sm[];
    float* sx = sm;
    float* sy = sm + NPTS;
    float* sz = sm + 2 * NPTS;
    int* sidx = (int*)(sm + 3 * NPTS);   // 8 warps * 32

    int dtI = blockIdx.x, g = blockIdx.y, half = blockIdx.z;
    int b = g >> 4, f = g & 15;
    int tid = threadIdx.x, warp = tid >> 5, lane = tid & 31;
    int* ib = sidx + warp * KNN;

    int t = 2 * f + dtI - 1;
    t = t < 0 ? 0 : (t > 31 ? 31 : t);
    const float* frame = xyzs + ((size_t)(b * 32 + t)) * NPTS * 3;
    for (int i = tid; i < NPTS; i += 256) {
        sx[i] = frame[3 * i + 0];
        sy[i] = frame[3 * i + 1];
        sz[i] = frame[3 * i + 2];
    }
    __syncthreads();

    unsigned lt = (1u << lane) - 1u;

    for (int mi = 0; mi < 8; mi++) {
        int m = half * 64 + mi * 8 + warp;
        const float* ap = anchors + ((size_t)g * MANCH + m) * 3;
        float ax = ap[0], ay = ap[1], az = ap[2];

        // first-KNN-within-radius, ascending index (exact semantics)
        int count = 0;
        for (int base = 0; base < NPTS && count < KNN; base += 128) {
            int i0 = base + lane * 4;
            float4 x4 = *(const float4*)&sx[i0];
            float4 y4 = *(const float4*)&sy[i0];
            float4 z4 = *(const float4*)&sz[i0];
            bool w0 = dist2_precise(ax, ay, az, x4.x, y4.x, z4.x) < RR2;
            bool w1 = dist2_precise(ax, ay, az, x4.y, y4.y, z4.y) < RR2;
            bool w2 = dist2_precise(ax, ay, az, x4.z, y4.z, z4.z) < RR2;
            bool w3 = dist2_precise(ax, ay, az, x4.w, y4.w, z4.w) < RR2;
            unsigned m0 = __ballot_sync(0xffffffffu, w0);
            unsigned m1 = __ballot_sync(0xffffffffu, w1);
            unsigned m2 = __ballot_sync(0xffffffffu, w2);
            unsigned m3 = __ballot_sync(0xffffffffu, w3);
            int r = count + __popc(m0 & lt) + __popc(m1 & lt)
                          + __popc(m2 & lt) + __popc(m3 & lt);
            if (w0) { if (r < KNN) ib[r] = i0;     r++; }
            if (w1) { if (r < KNN) ib[r] = i0 + 1; r++; }
            if (w2) { if (r < KNN) ib[r] = i0 + 2; r++; }
            if (w3) { if (r < KNN) ib[r] = i0 + 3; r++; }
            count += __popc(m0) + __popc(m1) + __popc(m2) + __popc(m3);
        }
        __syncwarp();
        int myIdx = 0;  // no valid neighbor -> index 0 (reference semantics)
        if (count > 0) myIdx = ib[lane < count ? lane : 0];

        float* dst = gDisp + (((size_t)g * MANCH + m) * 3 + dtI) * 96;
        dst[lane]      = sx[myIdx] - ax;
        dst[32 + lane] = sy[myIdx] - ay;
        dst[64 + lane] = sz[myIdx] - az;
        __syncwarp();
    }
}

// ---------------------------------------------------------------------------
// Kernel B2: layer1 (fp32) + layer2 fp16 m16n8k16 MMA + max-over-k + sum-dt.
// Grid (16,64), block 256 = 8 warps, warp = one anchor (3 dts in sequence).
// (R8 form: B fragments re-read from smem per mt — best measured variant.)
// ---------------------------------------------------------------------------
__global__ void __launch_bounds__(256, 3) mlp_kernel(float* __restrict__ out) {
    extern __shared__ uint32_t smB[];   // 8 warps * 16 frags * FS words
    int tile = blockIdx.x, g = blockIdx.y;
    int tid = threadIdx.x, warp = tid >> 5, lane = tid & 31;
    int gid = lane >> 2, tig = lane & 3;
    uint32_t* wB = smB + warp * 16 * FS;
    int m = tile * 8 + warp;

    // producer role: this lane is neighbor j = lane
    int ntp = lane >> 3, g8 = lane & 7;

    float accM[16];
#pragma unroll
    for (int i = 0; i < 16; i++) accM[i] = 0.0f;

    for (int dtI = 0; dtI < 3; dtI++) {
        const float* src = gDisp + (((size_t)g * MANCH + m) * 3 + dtI) * 96;
        float dx = src[lane], dy = src[32 + lane], dz = src[64 + lane];
        float dtf = (float)(dtI - 1);

        // ---- layer 1 (fp32) -> fp16 B fragments (fragment-major, FS pad)
#pragma unroll
        for (int kt = 0; kt < 4; kt++) {
            float hv[16];
#pragma unroll
            for (int c = 0; c < 16; c++) {
                float4 w = cWd[kt * 16 + c];
                float v = fmaf(w.x, dx, fmaf(w.y, dy, fmaf(w.z, dz, w.w * dtf)));
                hv[c] = fmaxf(v, 0.0f);
            }
#pragma unroll
            for (int tg = 0; tg < 4; tg++) {
                uint2 v;
                v.x = pkh2(hv[2 * tg],     hv[2 * tg + 1]);
                v.y = pkh2(hv[2 * tg + 8], hv[2 * tg + 9]);
                *(uint2*)(wB + (kt * 4 + ntp) * FS + (g8 * 4 + tg) * 2) = v;
            }
        }
        __syncwarp();

        // ---- layer 2: D[128 o x 32 k] via 128 mma.m16n8k16 (fp16)
#pragma unroll 1
        for (int mt = 0; mt < 8; mt++) {
            float d[4][4];
#pragma unroll
            for (int nt = 0; nt < 4; nt++)
#pragma unroll
                for (int r = 0; r < 4; r++) d[nt][r] = 0.0f;

#pragma unroll
            for (int kt = 0; kt < 4; kt++) {
                uint4 afr = *(const uint4*)&gWmF16[((mt * 4 + kt) * 32 + lane) * 4];
#pragma unroll
                for (int nt = 0; nt < 4; nt++) {
                    uint2 bf = *(const uint2*)(wB + (kt * 4 + nt) * FS + lane * 2);
                    mma_f16(d[nt][0], d[nt][1], d[nt][2], d[nt][3],
                            afr.x, afr.y, afr.z, afr.w, bf.x, bf.y);
                }
            }
            // epilogue: max over neighbors (cols), relu, accumulate over dt
            float mlo = fmaxf(d[0][0], d[0][1]);
            float mhi = fmaxf(d[0][2], d[0][3]);
#pragma unroll
            for (int nt = 1; nt < 4; nt++) {
                mlo = fmaxf(mlo, fmaxf(d[nt][0], d[nt][1]));
                mhi = fmaxf(mhi, fmaxf(d[nt][2], d[nt][3]));
            }
            mlo = fmaxf(mlo, __shfl_xor_sync(0xffffffffu, mlo, 1));
            mlo = fmaxf(mlo, __shfl_xor_sync(0xffffffffu, mlo, 2));
            mhi = fmaxf(mhi, __shfl_xor_sync(0xffffffffu, mhi, 1));
            mhi = fmaxf(mhi, __shfl_xor_sync(0xffffffffu, mhi, 2));
            accM[2 * mt]     += fmaxf(mlo, 0.0f);
            accM[2 * mt + 1] += fmaxf(mhi, 0.0f);
        }
        __syncwarp();  // reads done before next dt's producer overwrites
    }

    // ---- write new_features: out[b,f,o,m] after the new_xyzs block
    float* feat = out + (size_t)GTOT * MANCH * 3;
    if (tig == 0) {
#pragma unroll
        for (int mt = 0; mt < 8; mt++) {
            int o_lo = mt * 16 + gid;
            feat[((size_t)g * GC1 + o_lo) * MANCH + m]     = accM[2 * mt];
            feat[((size_t)g * GC1 + o_lo + 8) * MANCH + m] = accM[2 * mt + 1];
        }
    }
}

extern "C" void kernel_launch(void* const* d_in, const int* in_sizes, int n_in,
                              void* d_out, int out_size) {
    const float* xyzs = (const float*)d_in[0];
    const float* Wd   = (const float*)d_in[1];
    const float* Wm   = (const float*)d_in[2];
    float* out = (float*)d_out;

    cudaMemcpyToSymbolAsync(cWd, Wd, GC0 * 4 * sizeof(float), 0,
                            cudaMemcpyDeviceToDevice);

    size_t smF = (size_t)3 * NPTS * sizeof(float);                    // 48K
    size_t smQ = smF + (size_t)8 * KNN * sizeof(int);                 // 49K
    size_t smM = (size_t)8 * 16 * FS * sizeof(uint32_t);              // 33K

    cudaFuncSetAttribute(fps_kernel,   cudaFuncAttributeMaxDynamicSharedMemorySize, (int)smF);
    cudaFuncSetAttribute(query_kernel, cudaFuncAttributeMaxDynamicSharedMemorySize, (int)smQ);
    cudaFuncSetAttribute(mlp_kernel,   cudaFuncAttributeMaxDynamicSharedMemorySize, (int)smM);

    fps_kernel<<<GTOT + 4, FPS_THREADS, smF>>>(xyzs, Wm, out);   // fps + prep
    query_kernel<<<dim3(3, GTOT, 2), 256, smQ>>>(xyzs, out);
    mlp_kernel<<<dim3(16, GTOT), 256, smM>>>(out);
}